// round 11
// baseline (speedup 1.0000x reference)
#include <cuda_runtime.h>
#include <cuda_bf16.h>
#include <math.h>

// ------------------------------------------------------------------
// Problem constants
// ------------------------------------------------------------------
#define TT   4096
#define DD   128
#define HH   512
#define H3   1536
#define EE   256
#define WNW  4
#define NB   128          // persistent CTAs in scan (<=148 SMs -> co-resident)
#define NTH  640          // 20 warps: one per phase-A task
#define NGRP 16           // barrier groups
#define GSZ  8            // CTAs per group (NGRP*GSZ == NB)

// ------------------------------------------------------------------
// Device scratch (no cudaMalloc allowed anywhere)
// ------------------------------------------------------------------
__device__ float g_xW [TT * H3];                // x@W  + b
__device__ float g_xWa[TT * HH];                // x@Wa + ba
__device__ float g_gwX[(size_t)TT * WNW * H3];  // emb[ids]@Ww + bw
__device__ unsigned char g_mask[TT * WNW];      // canonicalized bool mask
__device__ int   g_any [TT];                    // any(mask) per step
__device__ float g_cw  [WNW * HH];              // per-step c_w exchange buffer

// Hierarchical barrier state: every word on its own 128B line so arrival
// atomics NEVER share a line with spin loads (the R9 barrier had g_count
// and g_gen adjacent -> one contended line for everything).
struct alignas(128) PadWord { unsigned int v; unsigned int pad[31]; };
__device__ PadWord g_grpCnt [NGRP];   // group arrival counters
__device__ PadWord g_grpFlag[NGRP];   // group release flags (generation)
__device__ PadWord g_rootCnt;         // root arrival counter

// ------------------------------------------------------------------
// Helpers
// ------------------------------------------------------------------
__device__ __forceinline__ float wsum(float v) {
#pragma unroll
    for (int o = 16; o; o >>= 1) v += __shfl_xor_sync(0xffffffffu, v, o);
    return v;
}
__device__ __forceinline__ float sigf(float x) { return 1.0f / (1.0f + expf(-x)); }

// Two-level grid barrier.
//   arrive : atomicAdd(group counter); group-last -> atomicAdd(root counter)
//   release: root-last resets all counters, then stores generation into all
//            16 group flags (independent lines, pipelined)
//   wait   : single thread per CTA spins on ITS group flag (<=8 spinners/line)
// Counter reset is safe before the flag store: no CTA can arrive at the next
// barrier until it observes this generation. Monotonic targets, never reset.
__device__ __forceinline__ void gbar(unsigned int target) {
    __syncthreads();
    if (threadIdx.x == 0) {
        const int grp = blockIdx.x >> 3;       // /GSZ
        __threadfence();                       // release own data
        unsigned int go = atomicAdd(&g_grpCnt[grp].v, 1u);
        if (go == GSZ - 1u) {
            unsigned int ro = atomicAdd(&g_rootCnt.v, 1u);
            if (ro == NGRP - 1u) {
                // root-last: reset counters, then release everyone
                atomicExch(&g_rootCnt.v, 0u);
#pragma unroll
                for (int g = 0; g < NGRP; g++) atomicExch(&g_grpCnt[g].v, 0u);
                __threadfence();
#pragma unroll
                for (int g = 0; g < NGRP; g++)
                    *(volatile unsigned int*)&g_grpFlag[g].v = target;
            } else {
                while (*(volatile unsigned int*)&g_grpFlag[grp].v < target) { }
            }
        } else {
            while (*(volatile unsigned int*)&g_grpFlag[grp].v < target) { }
        }
        __threadfence();                       // acquire others' data
    }
    __syncthreads();
}

// ------------------------------------------------------------------
// Barrier state reset (must run every launch: determinism across replays)
// ------------------------------------------------------------------
__global__ void reset_kernel() {
    if (threadIdx.x < NGRP) {
        g_grpCnt [threadIdx.x].v = 0u;
        g_grpFlag[threadIdx.x].v = 0u;
    }
    if (threadIdx.x == 0) g_rootCnt.v = 0u;
}

// ------------------------------------------------------------------
// word_mask dtype detection + canonicalization + any() precompute.
// Hypotheses: int32 (0/1 words), float32 (0.0/1.0 words), else uint8.
// ------------------------------------------------------------------
__global__ void mask_kernel(const unsigned char* __restrict__ raw) {
    __shared__ int s_notI32, s_notF32, s_mode;
    int tid = threadIdx.x;
    if (tid == 0) { s_notI32 = 0; s_notF32 = 0; }
    __syncthreads();

    const unsigned int* w = (const unsigned int*)raw;
    int li = 0, lf = 0;
    for (int i = tid; i < TT; i += blockDim.x) {
        unsigned int v = w[i];
        if (v != 0u && v != 1u)          li = 1;
        if (v != 0u && v != 0x3f800000u) lf = 1;
    }
    if (li) atomicOr(&s_notI32, 1);
    if (lf) atomicOr(&s_notF32, 1);
    __syncthreads();
    if (tid == 0) s_mode = (!s_notI32) ? 1 : ((!s_notF32) ? 2 : 0);
    __syncthreads();

    int mode = s_mode;
    for (int i = tid; i < TT * WNW; i += blockDim.x) {
        unsigned char m;
        if (mode == 1)      m = (((const int*)  raw)[i] != 0);
        else if (mode == 2) m = (((const float*)raw)[i] != 0.0f);
        else                m = (raw[i] != 0);
        g_mask[i] = m;
    }
    __syncthreads();
    for (int t = tid; t < TT; t += blockDim.x) {
        g_any[t] = (g_mask[4*t] | g_mask[4*t+1] | g_mask[4*t+2] | g_mask[4*t+3]) ? 1 : 0;
    }
}

// ------------------------------------------------------------------
// GEMM with optional A-row gather and bias:
//   C[M,N] = gather(A)[M,K] @ B[K,N] + bias[N]
// 128x128 tile, BK=16, 256 threads, 8x8 register microtile.
// ------------------------------------------------------------------
#define GBM 128
#define GBN 128
#define GBK 16
__global__ __launch_bounds__(256) void gemm_bias(
    const float* __restrict__ A, const float* __restrict__ B,
    const float* __restrict__ bias, float* __restrict__ C,
    int M, int N, int K, const int* __restrict__ gather)
{
    __shared__ float As[GBK][GBM];
    __shared__ float Bs[GBK][GBN];

    const int tid = threadIdx.x;
    const int bm0 = blockIdx.y * GBM, bn0 = blockIdx.x * GBN;
    const int tx = tid & 15, ty = tid >> 4;

    float acc[8][8];
#pragma unroll
    for (int i = 0; i < 8; i++)
#pragma unroll
        for (int j = 0; j < 8; j++) acc[i][j] = 0.0f;

    int arow[8];
#pragma unroll
    for (int i = 0; i < 8; i++) {
        int m = (tid + i * 256) >> 4;
        int r = bm0 + m;
        arow[i] = gather ? gather[r] : r;
    }

    for (int k0 = 0; k0 < K; k0 += GBK) {
#pragma unroll
        for (int i = 0; i < 8; i++) {
            int lin = tid + i * 256;
            int m = lin >> 4, kk = lin & 15;
            As[kk][m] = A[(size_t)arow[i] * K + k0 + kk];
        }
#pragma unroll
        for (int i = 0; i < 8; i++) {
            int lin = tid + i * 256;
            int kk = lin >> 7, n = lin & 127;
            Bs[kk][n] = B[(size_t)(k0 + kk) * N + bn0 + n];
        }
        __syncthreads();
#pragma unroll
        for (int kk = 0; kk < GBK; kk++) {
            float a[8], bb[8];
#pragma unroll
            for (int i = 0; i < 8; i++) a[i]  = As[kk][ty * 8 + i];
#pragma unroll
            for (int j = 0; j < 8; j++) bb[j] = Bs[kk][tx * 8 + j];
#pragma unroll
            for (int i = 0; i < 8; i++)
#pragma unroll
                for (int j = 0; j < 8; j++) acc[i][j] = fmaf(a[i], bb[j], acc[i][j]);
        }
        __syncthreads();
    }

#pragma unroll
    for (int i = 0; i < 8; i++) {
        int row = bm0 + ty * 8 + i;
#pragma unroll
        for (int j = 0; j < 8; j++) {
            int col = bn0 + tx * 8 + j;
            C[(size_t)row * N + col] = acc[i][j] + bias[col];
        }
    }
}

// ------------------------------------------------------------------
// Persistent scan kernel. 128 CTAs x 640 threads (20 warps). CTA bx owns
// hidden columns j0..j0+3. Each warp owns ONE phase-A triple-dot task and
// holds its 3x512 recurrent-weight column slice in REGISTERS (48 f/lane).
// h-vectors are streamed DIRECTLY from out[] (no smem staging): rows of
// out are write-once-then-read, so default L1 caching is safe, and L1 is
// flushed at every launch (graph replays included).
//
// warp 0..3  : main gates (i,o,g), vector h_{t-1},        weights U
// warp 4..19 : word-cell gates (f,i,g), w,dj decode,      weights Uw
//
// Per step:
//   phase A: register-weight dots -> s_iog / c_w -> g_cw (+ s_cwown)
//   gbar(2t+1)
//   phase B: alpha[w,dj] = sig(xWa + <c_w[w], Ua[:,dj]>)  (c_w via __ldcg)
//            warp 16 prefetches mask/any for the combine
//   combine: softmax-weighted cell, write out row t (doubles as Hbuf/Cbuf)
//   gbar(2t+2)   (publishes out[t]; protects g_cw reuse)
// ------------------------------------------------------------------
__global__ __launch_bounds__(NTH, 1) void scan_kernel(
    float* __restrict__ out,
    const int* __restrict__ wstarts,
    const float* __restrict__ h0,
    const float* __restrict__ c0,
    const float* __restrict__ U,
    const float* __restrict__ Uw,
    const float* __restrict__ Ua)
{
    __shared__ float sUa[4 * 512];      // Ua columns j0..j0+3
    __shared__ float s_iog[12];         // sig(i),sig(o),tanh(g) per dj
    __shared__ float s_alpha[16];       // alpha[w*4+dj]
    __shared__ float s_cwown[16];       // c_w[w, j0+dj] (own columns)
    __shared__ int   s_mask4[4];        // mask[t, 0..3]
    __shared__ int   s_anyt;            // any(mask[t])

    const int tid  = threadIdx.x;
    const int wg   = tid >> 5;
    const int lane = tid & 31;
    const int j0   = blockIdx.x * 4;

    // ---- one-time preload: Ua slice to smem ----
    for (int idx = tid; idx < 4 * 512; idx += NTH) {
        int dj = idx >> 9, k = idx & 511;
        sUa[idx] = Ua[(size_t)k * HH + j0 + dj];
    }

    // ---- one-time preload: per-warp gate weights to registers ----
    // lane l holds k = l + 32*m, m = 0..15, for this warp's 3 gate columns.
    const bool isU = (wg < 4);
    const int  dj  = isU ? wg : ((wg - 4) & 3);
    const int  wrd = isU ? 0  : ((wg - 4) >> 2);
    const int  jp  = j0 + dj;
    float wr0[16], wr1[16], wr2[16];
    {
        const float* M = isU ? U : Uw;
#pragma unroll
        for (int m = 0; m < 16; m++) {
            int k = lane + (m << 5);
            wr0[m] = M[(size_t)k * H3 + jp];
            wr1[m] = M[(size_t)k * H3 + 512 + jp];
            wr2[m] = M[(size_t)k * H3 + 1024 + jp];
        }
    }

    float cprev = (tid < 4) ? c0[j0 + tid] : 0.0f;   // register-carried c_{t-1}
    __syncthreads();

    for (int t = 0; t < TT; t++) {
        // ---- phase A: one register-weight triple-dot per warp, vector
        //      streamed straight from out[] (or h0 / zeros at t==0) ----
        {
            const float* vec;
            float csv = 0.0f;                    // c at word start (own col)
            bool  dovec = true;
            if (isU) {
                vec = (t == 0) ? h0 : (out + (size_t)(t - 1) * 1024);
            } else {
                int s = __ldg(&wstarts[t * WNW + wrd]);
                vec = out + (size_t)s * 1024;
                if (t == 0) dovec = false;       // Hbuf/Cbuf are zeros at t=0
                else if (lane == 0) csv = out[(size_t)s * 1024 + 512 + jp];
            }

            float add0 = 0.f, add1 = 0.f, add2 = 0.f;
            if (lane == 0) {                     // issued early, used after wsum
                const float* src = isU ? (g_xW + (size_t)t * H3)
                                       : (g_gwX + (size_t)(t * WNW + wrd) * H3);
                add0 = __ldg(src + jp);
                add1 = __ldg(src + 512 + jp);
                add2 = __ldg(src + 1024 + jp);
            }

            float a0 = 0.f, a1 = 0.f, a2 = 0.f;
            if (dovec) {
#pragma unroll
                for (int m = 0; m < 16; m++) {
                    float hv = vec[lane + (m << 5)];
                    a0 = fmaf(hv, wr0[m], a0);
                    a1 = fmaf(hv, wr1[m], a1);
                    a2 = fmaf(hv, wr2[m], a2);
                }
            }
            a0 = wsum(a0); a1 = wsum(a1); a2 = wsum(a2);
            if (lane == 0) {
                if (isU) {
                    s_iog[dj * 3 + 0] = sigf(add0 + a0);   // i (sigmoided)
                    s_iog[dj * 3 + 1] = sigf(add1 + a1);   // o
                    s_iog[dj * 3 + 2] = tanhf(add2 + a2);  // g (tanh'd)
                } else {
                    // gw split order: f, i, g
                    float cwv = sigf(add0 + a0) * csv
                              + sigf(add1 + a1) * tanhf(add2 + a2);
                    g_cw[wrd * 512 + jp] = cwv;
                    s_cwown[wrd * 4 + dj] = cwv;
                }
            }
        }
        gbar(2u * t + 1u);

        // ---- phase B: alpha dots, c_w streamed from L2 (rewritten data) ----
        if (wg < 16) {
            const int w2 = wg >> 2, dj2 = wg & 3;
            const int jp2 = j0 + dj2;
            float add = (lane == 0) ? __ldg(&g_xWa[(size_t)t * HH + jp2]) : 0.f;
            const float* cv = g_cw + w2 * 512;
            const float* ua = sUa + dj2 * 512;
            float a = 0.f;
#pragma unroll
            for (int m = 0; m < 16; m++) {
                int k = lane + (m << 5);
                a = fmaf(__ldcg(cv + k), ua[k], a);
            }
            a = wsum(a);
            if (lane == 0) s_alpha[wg] = sigf(add + a);
        } else if (wg == 16) {
            if (lane < 4) s_mask4[lane] = (int)g_mask[t * WNW + lane];
            if (lane == 4) s_anyt = g_any[t];
        }
        __syncthreads();

        // ---- final combine: 4 threads, one per owned column ----
        if (tid < 4) {
            const int dc = tid, jc = j0 + dc;
            float ig = s_iog[dc * 3 + 0];
            float og = s_iog[dc * 3 + 1];
            float gg = s_iog[dc * 3 + 2];
            float e0 = expf(ig);
            float se = e0, num = e0 * gg;
#pragma unroll
            for (int w = 0; w < WNW; w++) {
                if (s_mask4[w]) {
                    float ew = expf(s_alpha[w * 4 + dc]);
                    se += ew;
                    num = fmaf(ew, s_cwown[w * 4 + dc], num);
                }
            }
            float c1 = s_anyt ? (num / se)
                              : ((1.0f - ig) * cprev + ig * gg);
            float h1 = og * tanhf(c1);
            out[(size_t)t * 1024 + jc]       = h1;
            out[(size_t)t * 1024 + 512 + jc] = c1;
            cprev = c1;
        }
        gbar(2u * t + 2u);   // publish out[t] + protect g_cw reuse
    }
}

// ------------------------------------------------------------------
// Launch. Input order (metadata): x, word_ids, word_starts, word_mask,
// h0, c0, emb, W, U, b, Wa, Ua, ba, Ww, Uw, bw.  Output: [T, 2H] f32.
// ------------------------------------------------------------------
extern "C" void kernel_launch(void* const* d_in, const int* in_sizes, int n_in,
                              void* d_out, int out_size)
{
    const float*         x        = (const float*)d_in[0];
    const int*           word_ids = (const int*)  d_in[1];
    const int*           wstarts  = (const int*)  d_in[2];
    const unsigned char* mraw     = (const unsigned char*)d_in[3];
    const float*         h0       = (const float*)d_in[4];
    const float*         c0       = (const float*)d_in[5];
    const float*         emb      = (const float*)d_in[6];
    const float*         W        = (const float*)d_in[7];
    const float*         U        = (const float*)d_in[8];
    const float*         b        = (const float*)d_in[9];
    const float*         Wa       = (const float*)d_in[10];
    const float*         Ua       = (const float*)d_in[11];
    const float*         ba       = (const float*)d_in[12];
    const float*         Ww       = (const float*)d_in[13];
    const float*         Uw       = (const float*)d_in[14];
    const float*         bw       = (const float*)d_in[15];
    float*               out      = (float*)d_out;

    (void)in_sizes; (void)n_in; (void)out_size;

    void *pxW = nullptr, *pxWa = nullptr, *pgwX = nullptr;
    cudaGetSymbolAddress(&pxW,  g_xW);
    cudaGetSymbolAddress(&pxWa, g_xWa);
    cudaGetSymbolAddress(&pgwX, g_gwX);

    reset_kernel<<<1, 32>>>();
    mask_kernel<<<1, 1024>>>(mraw);

    // xW  = x @ W  + b    : [4096,128]@[128,1536]
    gemm_bias<<<dim3(H3 / GBN, TT / GBM), 256>>>(
        x, W, b, (float*)pxW, TT, H3, DD, nullptr);
    // xWa = x @ Wa + ba   : [4096,128]@[128,512]
    gemm_bias<<<dim3(HH / GBN, TT / GBM), 256>>>(
        x, Wa, ba, (float*)pxWa, TT, HH, DD, nullptr);
    // gwX = emb[word_ids] @ Ww + bw : [16384,256]@[256,1536]
    gemm_bias<<<dim3(H3 / GBN, (TT * WNW) / GBM), 256>>>(
        emb, Ww, bw, (float*)pgwX, TT * WNW, H3, EE, word_ids);

    scan_kernel<<<NB, NTH>>>(out, wstarts, h0, c0, U, Uw, Ua);
}

// round 12
// speedup vs baseline: 1.1295x; 1.1295x over previous
#include <cuda_runtime.h>
#include <cuda_bf16.h>
#include <math.h>

// ------------------------------------------------------------------
// Problem constants
// ------------------------------------------------------------------
#define TT   4096
#define DD   128
#define HH   512
#define H3   1536
#define EE   256
#define WNW  4
#define NB   128          // persistent CTAs in scan (<=148 SMs -> co-resident)
#define NTH  640          // 20 warps: one per phase-A task

// ------------------------------------------------------------------
// Device scratch (no cudaMalloc allowed anywhere)
// ------------------------------------------------------------------
__device__ float g_xW [TT * H3];                // x@W  + b
__device__ float g_xWa[TT * HH];                // x@Wa + ba
__device__ float g_gwX[(size_t)TT * WNW * H3];  // emb[ids]@Ww + bw
__device__ unsigned char g_mask[TT * WNW];      // canonicalized bool mask
__device__ int   g_any [TT];                    // any(mask) per step
__device__ float g_cw  [WNW * HH];              // per-step c_w exchange buffer

// Barrier words, each on its OWN 128B line (R9 had them adjacent: spin
// loads and arrival atomics fought over one LTS line).
struct alignas(128) PadWord { unsigned int v; unsigned int pad[31]; };
__device__ PadWord g_cntP;   // arrival counter
__device__ PadWord g_genP;   // generation flag (spun on)

// ------------------------------------------------------------------
// Helpers (fast-math transcendentals: MUFU-based, rel err ~2^-21)
// ------------------------------------------------------------------
__device__ __forceinline__ float wsum(float v) {
#pragma unroll
    for (int o = 16; o; o >>= 1) v += __shfl_xor_sync(0xffffffffu, v, o);
    return v;
}
__device__ __forceinline__ float fsig(float x) {
    return __fdividef(1.0f, 1.0f + __expf(-x));     // -inf->0, +inf->1 safe
}
__device__ __forceinline__ float ftanh(float x) {
    // overflow-safe: t = e^{-2|x|} in (0,1]
    float t = __expf(-2.0f * fabsf(x));
    float r = __fdividef(1.0f - t, 1.0f + t);
    return copysignf(r, x);
}

// Single-level grid barrier (R9 structure, padded lines). One atomicAdd
// arrival per CTA; 127 single-thread spinners on one dedicated flag line.
__device__ __forceinline__ void gbar(unsigned int target) {
    __syncthreads();
    if (threadIdx.x == 0) {
        __threadfence();
        unsigned int old = atomicAdd(&g_cntP.v, 1u);
        if (old == NB - 1u) {
            atomicExch(&g_cntP.v, 0u);
            __threadfence();
            *(volatile unsigned int*)&g_genP.v = target;   // release
        } else {
            while (*(volatile unsigned int*)&g_genP.v < target) { }
            __threadfence();                               // acquire
        }
    }
    __syncthreads();
}

// ------------------------------------------------------------------
// Barrier state reset (every launch: determinism across graph replays)
// ------------------------------------------------------------------
__global__ void reset_kernel() {
    g_cntP.v = 0u;
    g_genP.v = 0u;
}

// ------------------------------------------------------------------
// word_mask dtype detection + canonicalization + any() precompute.
// Hypotheses: int32 (0/1 words), float32 (0.0/1.0 words), else uint8.
// ------------------------------------------------------------------
__global__ void mask_kernel(const unsigned char* __restrict__ raw) {
    __shared__ int s_notI32, s_notF32, s_mode;
    int tid = threadIdx.x;
    if (tid == 0) { s_notI32 = 0; s_notF32 = 0; }
    __syncthreads();

    const unsigned int* w = (const unsigned int*)raw;
    int li = 0, lf = 0;
    for (int i = tid; i < TT; i += blockDim.x) {
        unsigned int v = w[i];
        if (v != 0u && v != 1u)          li = 1;
        if (v != 0u && v != 0x3f800000u) lf = 1;
    }
    if (li) atomicOr(&s_notI32, 1);
    if (lf) atomicOr(&s_notF32, 1);
    __syncthreads();
    if (tid == 0) s_mode = (!s_notI32) ? 1 : ((!s_notF32) ? 2 : 0);
    __syncthreads();

    int mode = s_mode;
    for (int i = tid; i < TT * WNW; i += blockDim.x) {
        unsigned char m;
        if (mode == 1)      m = (((const int*)  raw)[i] != 0);
        else if (mode == 2) m = (((const float*)raw)[i] != 0.0f);
        else                m = (raw[i] != 0);
        g_mask[i] = m;
    }
    __syncthreads();
    for (int t = tid; t < TT; t += blockDim.x) {
        g_any[t] = (g_mask[4*t] | g_mask[4*t+1] | g_mask[4*t+2] | g_mask[4*t+3]) ? 1 : 0;
    }
}

// ------------------------------------------------------------------
// GEMM with optional A-row gather and bias:
//   C[M,N] = gather(A)[M,K] @ B[K,N] + bias[N]
// 128x128 tile, BK=16, 256 threads, 8x8 register microtile.
// ------------------------------------------------------------------
#define GBM 128
#define GBN 128
#define GBK 16
__global__ __launch_bounds__(256) void gemm_bias(
    const float* __restrict__ A, const float* __restrict__ B,
    const float* __restrict__ bias, float* __restrict__ C,
    int M, int N, int K, const int* __restrict__ gather)
{
    __shared__ float As[GBK][GBM];
    __shared__ float Bs[GBK][GBN];

    const int tid = threadIdx.x;
    const int bm0 = blockIdx.y * GBM, bn0 = blockIdx.x * GBN;
    const int tx = tid & 15, ty = tid >> 4;

    float acc[8][8];
#pragma unroll
    for (int i = 0; i < 8; i++)
#pragma unroll
        for (int j = 0; j < 8; j++) acc[i][j] = 0.0f;

    int arow[8];
#pragma unroll
    for (int i = 0; i < 8; i++) {
        int m = (tid + i * 256) >> 4;
        int r = bm0 + m;
        arow[i] = gather ? gather[r] : r;
    }

    for (int k0 = 0; k0 < K; k0 += GBK) {
#pragma unroll
        for (int i = 0; i < 8; i++) {
            int lin = tid + i * 256;
            int m = lin >> 4, kk = lin & 15;
            As[kk][m] = A[(size_t)arow[i] * K + k0 + kk];
        }
#pragma unroll
        for (int i = 0; i < 8; i++) {
            int lin = tid + i * 256;
            int kk = lin >> 7, n = lin & 127;
            Bs[kk][n] = B[(size_t)(k0 + kk) * N + bn0 + n];
        }
        __syncthreads();
#pragma unroll
        for (int kk = 0; kk < GBK; kk++) {
            float a[8], bb[8];
#pragma unroll
            for (int i = 0; i < 8; i++) a[i]  = As[kk][ty * 8 + i];
#pragma unroll
            for (int j = 0; j < 8; j++) bb[j] = Bs[kk][tx * 8 + j];
#pragma unroll
            for (int i = 0; i < 8; i++)
#pragma unroll
                for (int j = 0; j < 8; j++) acc[i][j] = fmaf(a[i], bb[j], acc[i][j]);
        }
        __syncthreads();
    }

#pragma unroll
    for (int i = 0; i < 8; i++) {
        int row = bm0 + ty * 8 + i;
#pragma unroll
        for (int j = 0; j < 8; j++) {
            int col = bn0 + tx * 8 + j;
            C[(size_t)row * N + col] = acc[i][j] + bias[col];
        }
    }
}

// ------------------------------------------------------------------
// Persistent scan kernel. 128 CTAs x 640 threads (20 warps). CTA bx owns
// hidden columns j0..j0+3. Each warp owns ONE phase-A triple-dot task and
// holds its 3x512 recurrent-weight column slice in REGISTERS (48 f/lane).
// h-vectors are streamed DIRECTLY from out[] (write-once rows -> L1-safe;
// L1 is flushed per launch, graph replays included).
//
// NEW this round: all input-only per-step data (g_xW / g_gwX / g_xWa
// addends, wstarts, mask, any) is PREFETCHED one step ahead into registers
// so its DRAM latency hides across the barriers instead of sitting on the
// critical path.
//
// warp 0..3  : main gates (i,o,g), vector h_{t-1},   weights U
// warp 4..19 : word-cell gates (f,i,g),              weights Uw
// ------------------------------------------------------------------
__global__ __launch_bounds__(NTH, 1) void scan_kernel(
    float* __restrict__ out,
    const int* __restrict__ wstarts,
    const float* __restrict__ h0,
    const float* __restrict__ c0,
    const float* __restrict__ U,
    const float* __restrict__ Uw,
    const float* __restrict__ Ua)
{
    __shared__ float sUa[4 * 512];      // Ua columns j0..j0+3
    __shared__ float s_iog[12];         // sig(i),sig(o),tanh(g) per dj
    __shared__ float s_alpha[16];       // alpha[w*4+dj]
    __shared__ float s_cwown[16];       // c_w[w, j0+dj] (own columns)

    const int tid  = threadIdx.x;
    const int wg   = tid >> 5;
    const int lane = tid & 31;
    const int j0   = blockIdx.x * 4;

    // ---- one-time preload: Ua slice to smem ----
    for (int idx = tid; idx < 4 * 512; idx += NTH) {
        int dj = idx >> 9, k = idx & 511;
        sUa[idx] = Ua[(size_t)k * HH + j0 + dj];
    }

    // ---- one-time preload: per-warp gate weights to registers ----
    const bool isU = (wg < 4);
    const int  dj  = isU ? wg : ((wg - 4) & 3);
    const int  wrd = isU ? 0  : ((wg - 4) >> 2);
    const int  jp  = j0 + dj;
    float wr0[16], wr1[16], wr2[16];
    {
        const float* M = isU ? U : Uw;
#pragma unroll
        for (int m = 0; m < 16; m++) {
            int k = lane + (m << 5);
            wr0[m] = M[(size_t)k * H3 + jp];
            wr1[m] = M[(size_t)k * H3 + 512 + jp];
            wr2[m] = M[(size_t)k * H3 + 1024 + jp];
        }
    }

    // ---- prefetch registers, loaded for t=0 up front ----
    float pa0 = 0.f, pa1 = 0.f, pa2 = 0.f;   // phase-A addends (lane 0)
    float pxwa = 0.f;                        // phase-B addend (wg<16, lane 0)
    int   pws = 0;                           // word start (word warps, all lanes)
    unsigned int pmaskw = 0u;                // mask word for step t (tid<4)
    int   panyt = 0;                         // any(mask) for step t (tid<4)

    if (lane == 0) {
        const float* src = isU ? g_xW : (g_gwX + (size_t)wrd * H3);
        pa0 = __ldg(src + jp);
        pa1 = __ldg(src + 512 + jp);
        pa2 = __ldg(src + 1024 + jp);
    }
    if (!isU) pws = __ldg(&wstarts[wrd]);
    if (wg < 16 && lane == 0) pxwa = __ldg(&g_xWa[j0 + (wg & 3)]);
    if (tid < 4) {
        pmaskw = *(const unsigned int*)&g_mask[0];
        panyt  = g_any[0];
    }

    float cprev = (tid < 4) ? c0[j0 + tid] : 0.0f;   // register-carried c_{t-1}
    __syncthreads();

    for (int t = 0; t < TT; t++) {
        const int tn = (t + 1 < TT) ? t + 1 : t;     // prefetch target (clamped)

        // ---- phase A: one register-weight triple-dot per warp ----
        {
            const float* vec;
            float csv = 0.0f;                    // c at word start (own col)
            bool  dovec = true;
            if (isU) {
                vec = (t == 0) ? h0 : (out + (size_t)(t - 1) * 1024);
            } else {
                int s = pws;
                vec = out + (size_t)s * 1024;
                if (t == 0) dovec = false;       // Hbuf/Cbuf are zeros at t=0
                else if (lane == 0) csv = out[(size_t)s * 1024 + 512 + jp];
            }

            // consume current addends, then immediately issue t+1 prefetch
            float add0 = pa0, add1 = pa1, add2 = pa2;
            if (lane == 0) {
                const float* src = isU ? (g_xW + (size_t)tn * H3)
                                       : (g_gwX + (size_t)(tn * WNW + wrd) * H3);
                pa0 = __ldg(src + jp);
                pa1 = __ldg(src + 512 + jp);
                pa2 = __ldg(src + 1024 + jp);
            }
            if (!isU) pws = __ldg(&wstarts[tn * WNW + wrd]);

            float a0 = 0.f, a1 = 0.f, a2 = 0.f;
            if (dovec) {
#pragma unroll
                for (int m = 0; m < 16; m++) {
                    float hv = vec[lane + (m << 5)];
                    a0 = fmaf(hv, wr0[m], a0);
                    a1 = fmaf(hv, wr1[m], a1);
                    a2 = fmaf(hv, wr2[m], a2);
                }
            }
            a0 = wsum(a0); a1 = wsum(a1); a2 = wsum(a2);
            if (lane == 0) {
                if (isU) {
                    s_iog[dj * 3 + 0] = fsig(add0 + a0);    // i (sigmoided)
                    s_iog[dj * 3 + 1] = fsig(add1 + a1);    // o
                    s_iog[dj * 3 + 2] = ftanh(add2 + a2);   // g (tanh'd)
                } else {
                    // gw split order: f, i, g
                    float cwv = fsig(add0 + a0) * csv
                              + fsig(add1 + a1) * ftanh(add2 + a2);
                    g_cw[wrd * 512 + jp] = cwv;
                    s_cwown[wrd * 4 + dj] = cwv;
                }
            }
        }
        gbar(2u * t + 1u);

        // ---- phase B: alpha dots, c_w streamed from L2 (rewritten data) ----
        if (wg < 16) {
            const int w2 = wg >> 2, dj2 = wg & 3;
            float add = (lane == 0) ? pxwa : 0.f;
            if (lane == 0) pxwa = __ldg(&g_xWa[(size_t)tn * HH + j0 + dj2]);
            const float* cv = g_cw + w2 * 512;
            const float* ua = sUa + dj2 * 512;
            float a = 0.f;
#pragma unroll
            for (int m = 0; m < 16; m++) {
                int k = lane + (m << 5);
                a = fmaf(__ldcg(cv + k), ua[k], a);
            }
            a = wsum(a);
            if (lane == 0) s_alpha[wg] = fsig(add + a);
        }
        __syncthreads();

        // ---- final combine: 4 threads, one per owned column ----
        if (tid < 4) {
            const int dc = tid, jc = j0 + dc;
            float ig = s_iog[dc * 3 + 0];
            float og = s_iog[dc * 3 + 1];
            float gg = s_iog[dc * 3 + 2];
            float e0 = __expf(ig);
            float se = e0, num = e0 * gg;
#pragma unroll
            for (int w = 0; w < WNW; w++) {
                if ((pmaskw >> (8 * w)) & 0xffu) {
                    float ew = __expf(s_alpha[w * 4 + dc]);
                    se += ew;
                    num = fmaf(ew, s_cwown[w * 4 + dc], num);
                }
            }
            float c1 = panyt ? __fdividef(num, se)
                             : ((1.0f - ig) * cprev + ig * gg);
            float h1 = og * ftanh(c1);
            out[(size_t)t * 1024 + jc]       = h1;
            out[(size_t)t * 1024 + 512 + jc] = c1;
            cprev = c1;
            // prefetch mask/any for t+1
            pmaskw = *(const unsigned int*)&g_mask[tn * WNW];
            panyt  = g_any[tn];
        }
        gbar(2u * t + 2u);   // publish out[t] + protect g_cw reuse
    }
}

// ------------------------------------------------------------------
// Launch. Input order (metadata): x, word_ids, word_starts, word_mask,
// h0, c0, emb, W, U, b, Wa, Ua, ba, Ww, Uw, bw.  Output: [T, 2H] f32.
// ------------------------------------------------------------------
extern "C" void kernel_launch(void* const* d_in, const int* in_sizes, int n_in,
                              void* d_out, int out_size)
{
    const float*         x        = (const float*)d_in[0];
    const int*           word_ids = (const int*)  d_in[1];
    const int*           wstarts  = (const int*)  d_in[2];
    const unsigned char* mraw     = (const unsigned char*)d_in[3];
    const float*         h0       = (const float*)d_in[4];
    const float*         c0       = (const float*)d_in[5];
    const float*         emb      = (const float*)d_in[6];
    const float*         W        = (const float*)d_in[7];
    const float*         U        = (const float*)d_in[8];
    const float*         b        = (const float*)d_in[9];
    const float*         Wa       = (const float*)d_in[10];
    const float*         Ua       = (const float*)d_in[11];
    const float*         ba       = (const float*)d_in[12];
    const float*         Ww       = (const float*)d_in[13];
    const float*         Uw       = (const float*)d_in[14];
    const float*         bw       = (const float*)d_in[15];
    float*               out      = (float*)d_out;

    (void)in_sizes; (void)n_in; (void)out_size;

    void *pxW = nullptr, *pxWa = nullptr, *pgwX = nullptr;
    cudaGetSymbolAddress(&pxW,  g_xW);
    cudaGetSymbolAddress(&pxWa, g_xWa);
    cudaGetSymbolAddress(&pgwX, g_gwX);

    reset_kernel<<<1, 32>>>();
    mask_kernel<<<1, 1024>>>(mraw);

    // xW  = x @ W  + b    : [4096,128]@[128,1536]
    gemm_bias<<<dim3(H3 / GBN, TT / GBM), 256>>>(
        x, W, b, (float*)pxW, TT, H3, DD, nullptr);
    // xWa = x @ Wa + ba   : [4096,128]@[128,512]
    gemm_bias<<<dim3(HH / GBN, TT / GBM), 256>>>(
        x, Wa, ba, (float*)pxWa, TT, HH, DD, nullptr);
    // gwX = emb[word_ids] @ Ww + bw : [16384,256]@[256,1536]
    gemm_bias<<<dim3(H3 / GBN, (TT * WNW) / GBM), 256>>>(
        emb, Ww, bw, (float*)pgwX, TT * WNW, H3, EE, word_ids);

    scan_kernel<<<NB, NTH>>>(out, wstarts, h0, c0, U, Uw, Ua);
}

// round 14
// speedup vs baseline: 1.4629x; 1.2952x over previous
#include <cuda_runtime.h>
#include <cuda_bf16.h>
#include <math.h>

// ------------------------------------------------------------------
// Problem constants
// ------------------------------------------------------------------
#define TT   4096
#define DD   128
#define HH   512
#define H3   1536
#define EE   256
#define WNW  4
#define NB   128          // persistent CTAs in scan (<=148 SMs -> co-resident)
#define NTH  640          // 20 warps: one per phase-A task

// ------------------------------------------------------------------
// Device scratch (no cudaMalloc allowed anywhere)
// ------------------------------------------------------------------
__device__ float g_xW [TT * H3];                // x@W  + b
__device__ float g_xWa[TT * HH];                // x@Wa + ba
__device__ float g_gwX[(size_t)TT * WNW * H3];  // emb[ids]@Ww + bw
__device__ unsigned char g_mask[TT * WNW];      // canonicalized bool mask
__device__ int   g_any [TT];                    // any(mask) per step
__device__ float g_cw  [WNW * HH];              // per-step c_w exchange buffer

// Monotonic barrier counter on its own 128B line. Never reset mid-kernel:
// barrier k completes when count reaches k*NB. Arrival is a fire-and-forget
// RED; spinners poll the counter itself (no separate flag, no reset hop).
struct alignas(128) PadWord { unsigned int v; unsigned int pad[31]; };
__device__ PadWord g_cnt;

// ------------------------------------------------------------------
// Helpers (fast-math transcendentals: MUFU-based, rel err ~2^-21)
// ------------------------------------------------------------------
__device__ __forceinline__ float wsum(float v) {
#pragma unroll
    for (int o = 16; o; o >>= 1) v += __shfl_xor_sync(0xffffffffu, v, o);
    return v;
}
__device__ __forceinline__ float fsig(float x) {
    return __fdividef(1.0f, 1.0f + __expf(-x));     // -inf->0, +inf->1 safe
}
__device__ __forceinline__ float ftanh(float x) {
    float t = __expf(-2.0f * fabsf(x));             // overflow-safe form
    float r = __fdividef(1.0f - t, 1.0f + t);
    return copysignf(r, x);
}

// Barrier core: tid0 arrives (RED) and spins with nanosleep backoff until
// the monotonic counter reaches target. Backoff decongests the LTS line so
// the release (the last RED) and the observing polls aren't queued behind
// a 127-spinner poll storm.
__device__ __forceinline__ void gbar_core(unsigned int target) {
    if (threadIdx.x == 0) {
        __threadfence();
        atomicAdd(&g_cnt.v, 1u);                    // RED (result unused)
        if (*(volatile unsigned int*)&g_cnt.v < target) {
            unsigned int ns = 32u;
            do {
                __nanosleep(ns);
                if (ns < 256u) ns <<= 1;
            } while (*(volatile unsigned int*)&g_cnt.v < target);
        }
        __threadfence();
    }
    __syncthreads();
}
// Full barrier: writers are spread across warps -> entry syncthreads.
__device__ __forceinline__ void gbar_full(unsigned int target) {
    __syncthreads();
    gbar_core(target);
}
// Combine barrier: writers are warp 0 only -> entry syncwarp.
__device__ __forceinline__ void gbar_w0(unsigned int target) {
    if (threadIdx.x < 32) __syncwarp();
    gbar_core(target);
}

// ------------------------------------------------------------------
// Barrier state reset (every launch: determinism across graph replays)
// ------------------------------------------------------------------
__global__ void reset_kernel() { g_cnt.v = 0u; }

// ------------------------------------------------------------------
// word_mask dtype detection + canonicalization + any() precompute.
// Hypotheses: int32 (0/1 words), float32 (0.0/1.0 words), else uint8.
// ------------------------------------------------------------------
__global__ void mask_kernel(const unsigned char* __restrict__ raw) {
    __shared__ int s_notI32, s_notF32, s_mode;
    int tid = threadIdx.x;
    if (tid == 0) { s_notI32 = 0; s_notF32 = 0; }
    __syncthreads();

    const unsigned int* w = (const unsigned int*)raw;
    int li = 0, lf = 0;
    for (int i = tid; i < TT; i += blockDim.x) {
        unsigned int v = w[i];
        if (v != 0u && v != 1u)          li = 1;
        if (v != 0u && v != 0x3f800000u) lf = 1;
    }
    if (li) atomicOr(&s_notI32, 1);
    if (lf) atomicOr(&s_notF32, 1);
    __syncthreads();
    if (tid == 0) s_mode = (!s_notI32) ? 1 : ((!s_notF32) ? 2 : 0);
    __syncthreads();

    int mode = s_mode;
    for (int i = tid; i < TT * WNW; i += blockDim.x) {
        unsigned char m;
        if (mode == 1)      m = (((const int*)  raw)[i] != 0);
        else if (mode == 2) m = (((const float*)raw)[i] != 0.0f);
        else                m = (raw[i] != 0);
        g_mask[i] = m;
    }
    __syncthreads();
    for (int t = tid; t < TT; t += blockDim.x) {
        g_any[t] = (g_mask[4*t] | g_mask[4*t+1] | g_mask[4*t+2] | g_mask[4*t+3]) ? 1 : 0;
    }
}

// ------------------------------------------------------------------
// GEMM with optional A-row gather and bias:
//   C[M,N] = gather(A)[M,K] @ B[K,N] + bias[N]
// 128x128 tile, BK=16, 256 threads, 8x8 register microtile.
// ------------------------------------------------------------------
#define GBM 128
#define GBN 128
#define GBK 16
__global__ __launch_bounds__(256) void gemm_bias(
    const float* __restrict__ A, const float* __restrict__ B,
    const float* __restrict__ bias, float* __restrict__ C,
    int M, int N, int K, const int* __restrict__ gather)
{
    __shared__ float As[GBK][GBM];
    __shared__ float Bs[GBK][GBN];

    const int tid = threadIdx.x;
    const int bm0 = blockIdx.y * GBM, bn0 = blockIdx.x * GBN;
    const int tx = tid & 15, ty = tid >> 4;

    float acc[8][8];
#pragma unroll
    for (int i = 0; i < 8; i++)
#pragma unroll
        for (int j = 0; j < 8; j++) acc[i][j] = 0.0f;

    int arow[8];
#pragma unroll
    for (int i = 0; i < 8; i++) {
        int m = (tid + i * 256) >> 4;
        int r = bm0 + m;
        arow[i] = gather ? gather[r] : r;
    }

    for (int k0 = 0; k0 < K; k0 += GBK) {
#pragma unroll
        for (int i = 0; i < 8; i++) {
            int lin = tid + i * 256;
            int m = lin >> 4, kk = lin & 15;
            As[kk][m] = A[(size_t)arow[i] * K + k0 + kk];
        }
#pragma unroll
        for (int i = 0; i < 8; i++) {
            int lin = tid + i * 256;
            int kk = lin >> 7, n = lin & 127;
            Bs[kk][n] = B[(size_t)(k0 + kk) * N + bn0 + n];
        }
        __syncthreads();
#pragma unroll
        for (int kk = 0; kk < GBK; kk++) {
            float a[8], bb[8];
#pragma unroll
            for (int i = 0; i < 8; i++) a[i]  = As[kk][ty * 8 + i];
#pragma unroll
            for (int j = 0; j < 8; j++) bb[j] = Bs[kk][tx * 8 + j];
#pragma unroll
            for (int i = 0; i < 8; i++)
#pragma unroll
                for (int j = 0; j < 8; j++) acc[i][j] = fmaf(a[i], bb[j], acc[i][j]);
        }
        __syncthreads();
    }

#pragma unroll
    for (int i = 0; i < 8; i++) {
        int row = bm0 + ty * 8 + i;
#pragma unroll
        for (int j = 0; j < 8; j++) {
            int col = bn0 + tx * 8 + j;
            C[(size_t)row * N + col] = acc[i][j] + bias[col];
        }
    }
}

// ------------------------------------------------------------------
// Persistent scan kernel. 128 CTAs x 640 threads (20 warps). CTA bx owns
// hidden columns j0..j0+3. Each warp owns ONE phase-A triple-dot task and
// holds its 3x512 recurrent-weight column slice in REGISTERS (48 f/lane).
// h-vectors stream DIRECTLY from out[] (write-once rows -> cache-safe).
// All input-only per-step data is prefetched one step ahead.
//
// NEW: steps with any(mask[t])==0 skip barrier 1 + phase B entirely
// (identical control flow in all CTAs since g_any is global; barrier
// generations counted locally). Combine is 16-lane parallel.
// ------------------------------------------------------------------
__global__ __launch_bounds__(NTH, 1) void scan_kernel(
    float* __restrict__ out,
    const int* __restrict__ wstarts,
    const float* __restrict__ h0,
    const float* __restrict__ c0,
    const float* __restrict__ U,
    const float* __restrict__ Uw,
    const float* __restrict__ Ua)
{
    __shared__ float sUa[4 * 512];      // Ua columns j0..j0+3
    __shared__ float s_iog[12];         // sig(i),sig(o),tanh(g) per dj
    __shared__ float s_alpha[16];       // alpha[w*4+dj]
    __shared__ float s_cwown[16];       // c_w[w, j0+dj] (own columns)

    const int tid  = threadIdx.x;
    const int wg   = tid >> 5;
    const int lane = tid & 31;
    const int j0   = blockIdx.x * 4;

    // ---- one-time preload: Ua slice to smem ----
    for (int idx = tid; idx < 4 * 512; idx += NTH) {
        int dj = idx >> 9, k = idx & 511;
        sUa[idx] = Ua[(size_t)k * HH + j0 + dj];
    }

    // ---- one-time preload: per-warp gate weights to registers ----
    const bool isU = (wg < 4);
    const int  dj  = isU ? wg : ((wg - 4) & 3);
    const int  wrd = isU ? 0  : ((wg - 4) >> 2);
    const int  jp  = j0 + dj;
    float wr0[16], wr1[16], wr2[16];
    {
        const float* M = isU ? U : Uw;
#pragma unroll
        for (int m = 0; m < 16; m++) {
            int k = lane + (m << 5);
            wr0[m] = M[(size_t)k * H3 + jp];
            wr1[m] = M[(size_t)k * H3 + 512 + jp];
            wr2[m] = M[(size_t)k * H3 + 1024 + jp];
        }
    }

    // ---- prefetch registers, loaded for t=0 up front ----
    float pa0 = 0.f, pa1 = 0.f, pa2 = 0.f;   // phase-A addends (lane 0)
    float pxwa = 0.f;                        // phase-B addend (wg<16, lane 0)
    int   pws = 0;                           // word start (word warps)
    unsigned int pmaskw = 0u;                // mask word (warp 0, all lanes)
    int   panyt = 0;                         // any(mask) (all threads)

    if (lane == 0) {
        const float* src = isU ? g_xW : (g_gwX + (size_t)wrd * H3);
        pa0 = __ldg(src + jp);
        pa1 = __ldg(src + 512 + jp);
        pa2 = __ldg(src + 1024 + jp);
    }
    if (!isU) pws = __ldg(&wstarts[wrd]);
    if (wg < 16 && lane == 0) pxwa = __ldg(&g_xWa[j0 + (wg & 3)]);
    if (wg == 0) pmaskw = *(const unsigned int*)&g_mask[0];
    panyt = g_any[0];

    float cprev = (tid < 4) ? c0[j0 + tid] : 0.0f;   // register-carried c_{t-1}
    unsigned int nbar = 0u;                          // local barrier generation
    __syncthreads();

    for (int t = 0; t < TT; t++) {
        const int tn = (t + 1 < TT) ? t + 1 : t;     // prefetch target (clamped)
        const int cur_any = panyt;
        panyt = g_any[tn];                           // rotate (tiny, cached)

        // ---- phase A: one register-weight triple-dot per warp ----
        float addb = pxwa;                           // phase-B addend for step t
        {
            const bool active = isU || (cur_any != 0);
            const float* vec;
            float csv = 0.0f;
            bool  dovec = active;
            if (isU) {
                vec = (t == 0) ? h0 : (out + (size_t)(t - 1) * 1024);
            } else {
                int s = pws;
                vec = out + (size_t)s * 1024;
                if (t == 0) dovec = false;
                else if (active && lane == 0) csv = out[(size_t)s * 1024 + 512 + jp];
            }

            // consume current addends, then immediately issue t+1 prefetch
            float add0 = pa0, add1 = pa1, add2 = pa2;
            if (lane == 0) {
                const float* src = isU ? (g_xW + (size_t)tn * H3)
                                       : (g_gwX + (size_t)(tn * WNW + wrd) * H3);
                pa0 = __ldg(src + jp);
                pa1 = __ldg(src + 512 + jp);
                pa2 = __ldg(src + 1024 + jp);
            }
            if (!isU) pws = __ldg(&wstarts[tn * WNW + wrd]);
            if (wg < 16 && lane == 0)
                pxwa = __ldg(&g_xWa[(size_t)tn * HH + j0 + (wg & 3)]);

            float a0 = 0.f, a1 = 0.f, a2 = 0.f;
            if (dovec && t > 0 || (isU && t == 0)) {
#pragma unroll
                for (int m = 0; m < 16; m++) {
                    float hv = vec[lane + (m << 5)];
                    a0 = fmaf(hv, wr0[m], a0);
                    a1 = fmaf(hv, wr1[m], a1);
                    a2 = fmaf(hv, wr2[m], a2);
                }
            }
            a0 = wsum(a0); a1 = wsum(a1); a2 = wsum(a2);
            if (lane == 0) {
                if (isU) {
                    s_iog[dj * 3 + 0] = fsig(add0 + a0);    // i (sigmoided)
                    s_iog[dj * 3 + 1] = fsig(add1 + a1);    // o
                    s_iog[dj * 3 + 2] = ftanh(add2 + a2);   // g (tanh'd)
                } else if (active) {
                    // gw split order: f, i, g
                    float cwv = fsig(add0 + a0) * csv
                              + fsig(add1 + a1) * ftanh(add2 + a2);
                    g_cw[wrd * 512 + jp] = cwv;
                    s_cwown[wrd * 4 + dj] = cwv;
                }
            }
        }

        if (cur_any) {
            gbar_full(++nbar * NB);       // publish g_cw

            // ---- phase B: alpha dots, c_w streamed from L2 ----
            if (wg < 16) {
                const int w2 = wg >> 2, dj2 = wg & 3;
                float add = (lane == 0) ? addb : 0.f;
                const float* cv = g_cw + w2 * 512;
                const float* ua = sUa + dj2 * 512;
                float a = 0.f;
#pragma unroll
                for (int m = 0; m < 16; m++) {
                    int k = lane + (m << 5);
                    a = fmaf(__ldcg(cv + k), ua[k], a);
                }
                a = wsum(a);
                if (lane == 0) s_alpha[wg] = fsig(add + a);
            }
            __syncthreads();
        } else {
            __syncthreads();              // make s_iog visible to combine
        }

        // ---- combine: warp 0, 16-lane parallel softmax-merge ----
        if (wg == 0) {
            unsigned int cur_mask = pmaskw;
            pmaskw = *(const unsigned int*)&g_mask[tn * WNW];   // rotate
            const int w  = (lane >> 2) & 3;
            const int dc = lane & 3;
            float ew = 0.f, nm = 0.f;
            if (cur_any && ((cur_mask >> (8 * w)) & 0xffu)) {
                ew = __expf(s_alpha[w * 4 + dc]);
                nm = ew * s_cwown[w * 4 + dc];
            }
            ew += __shfl_xor_sync(0xffffffffu, ew, 4);
            nm += __shfl_xor_sync(0xffffffffu, nm, 4);
            ew += __shfl_xor_sync(0xffffffffu, ew, 8);
            nm += __shfl_xor_sync(0xffffffffu, nm, 8);
            if (lane < 4) {
                float ig = s_iog[lane * 3 + 0];
                float og = s_iog[lane * 3 + 1];
                float gg = s_iog[lane * 3 + 2];
                float c1;
                if (cur_any) {
                    float e0 = __expf(ig);
                    c1 = __fdividef(fmaf(e0, gg, nm), e0 + ew);
                } else {
                    c1 = (1.0f - ig) * cprev + ig * gg;
                }
                float h1 = og * ftanh(c1);
                out[(size_t)t * 1024 + j0 + lane]       = h1;
                out[(size_t)t * 1024 + 512 + j0 + lane] = c1;
                cprev = c1;
            }
        }
        gbar_w0(++nbar * NB);             // publish out[t]; protect g_cw reuse
    }
}

// ------------------------------------------------------------------
// Launch. Input order (metadata): x, word_ids, word_starts, word_mask,
// h0, c0, emb, W, U, b, Wa, Ua, ba, Ww, Uw, bw.  Output: [T, 2H] f32.
// ------------------------------------------------------------------
extern "C" void kernel_launch(void* const* d_in, const int* in_sizes, int n_in,
                              void* d_out, int out_size)
{
    const float*         x        = (const float*)d_in[0];
    const int*           word_ids = (const int*)  d_in[1];
    const int*           wstarts  = (const int*)  d_in[2];
    const unsigned char* mraw     = (const unsigned char*)d_in[3];
    const float*         h0       = (const float*)d_in[4];
    const float*         c0       = (const float*)d_in[5];
    const float*         emb      = (const float*)d_in[6];
    const float*         W        = (const float*)d_in[7];
    const float*         U        = (const float*)d_in[8];
    const float*         b        = (const float*)d_in[9];
    const float*         Wa       = (const float*)d_in[10];
    const float*         Ua       = (const float*)d_in[11];
    const float*         ba       = (const float*)d_in[12];
    const float*         Ww       = (const float*)d_in[13];
    const float*         Uw       = (const float*)d_in[14];
    const float*         bw       = (const float*)d_in[15];
    float*               out      = (float*)d_out;

    (void)in_sizes; (void)n_in; (void)out_size;

    void *pxW = nullptr, *pxWa = nullptr, *pgwX = nullptr;
    cudaGetSymbolAddress(&pxW,  g_xW);
    cudaGetSymbolAddress(&pxWa, g_xWa);
    cudaGetSymbolAddress(&pgwX, g_gwX);

    reset_kernel<<<1, 32>>>();
    mask_kernel<<<1, 1024>>>(mraw);

    // xW  = x @ W  + b    : [4096,128]@[128,1536]
    gemm_bias<<<dim3(H3 / GBN, TT / GBM), 256>>>(
        x, W, b, (float*)pxW, TT, H3, DD, nullptr);
    // xWa = x @ Wa + ba   : [4096,128]@[128,512]
    gemm_bias<<<dim3(HH / GBN, TT / GBM), 256>>>(
        x, Wa, ba, (float*)pxWa, TT, HH, DD, nullptr);
    // gwX = emb[word_ids] @ Ww + bw : [16384,256]@[256,1536]
    gemm_bias<<<dim3(H3 / GBN, (TT * WNW) / GBM), 256>>>(
        emb, Ww, bw, (float*)pgwX, TT * WNW, H3, EE, word_ids);

    scan_kernel<<<NB, NTH>>>(out, wstarts, h0, c0, U, Uw, Ua);
}

// round 15
// speedup vs baseline: 1.7097x; 1.1687x over previous
#include <cuda_runtime.h>
#include <cuda_bf16.h>
#include <math.h>

// ------------------------------------------------------------------
// Problem constants
// ------------------------------------------------------------------
#define TT   4096
#define DD   128
#define HH   512
#define H3   1536
#define EE   256
#define WNW  4
#define NB   128          // persistent CTAs in scan (<=148 SMs -> co-resident)
#define NTH  640          // 20 warps

// ------------------------------------------------------------------
// Device scratch (no cudaMalloc allowed anywhere)
// ------------------------------------------------------------------
__device__ float g_xW [TT * H3];                // x@W  + b
__device__ float g_xWa[TT * HH];                // x@Wa + ba
__device__ float g_gwX[(size_t)TT * WNW * H3];  // emb[ids]@Ww + bw
__device__ unsigned char g_mask[TT * WNW];      // canonicalized bool mask
__device__ int   g_any [TT];                    // any(mask) per step
__device__ int   g_nb1 [TT];                    // step has masked word w/ start==t-1
__device__ float g_cw  [2][WNW * HH];           // c_w exchange, double-buffered by t&1

// Monotonic barrier counter on its own 128B line. Reset by a trailing
// kernel after the scan (zero-init guarantees first-ever launch is clean).
struct alignas(128) PadWord { unsigned int v; unsigned int pad[31]; };
__device__ PadWord g_cnt;

// ------------------------------------------------------------------
// Helpers (fast-math transcendentals: MUFU-based, rel err ~2^-21)
// ------------------------------------------------------------------
__device__ __forceinline__ float wsum(float v) {
#pragma unroll
    for (int o = 16; o; o >>= 1) v += __shfl_xor_sync(0xffffffffu, v, o);
    return v;
}
__device__ __forceinline__ float fsig(float x) {
    return __fdividef(1.0f, 1.0f + __expf(-x));
}
__device__ __forceinline__ float ftanh(float x) {
    float t = __expf(-2.0f * fabsf(x));             // overflow-safe
    float r = __fdividef(1.0f - t, 1.0f + t);
    return copysignf(r, x);
}

// Grid barrier: monotonic counter, fire-and-forget arrival, fixed short
// sleep between polls (wake quantization ~64-128ns, traffic ~2x below
// tight spin). Entry syncthreads: writers are spread across warps.
__device__ __forceinline__ void gbar_full(unsigned int target) {
    __syncthreads();
    if (threadIdx.x == 0) {
        __threadfence();
        atomicAdd(&g_cnt.v, 1u);
        while (*(volatile unsigned int*)&g_cnt.v < target) __nanosleep(64);
        __threadfence();
    }
    __syncthreads();
}

// ------------------------------------------------------------------
// Barrier reset — launched AFTER the scan (next replay starts clean)
// ------------------------------------------------------------------
__global__ void reset_kernel() { g_cnt.v = 0u; }

// ------------------------------------------------------------------
// GEMM with optional A-row gather and bias (unchanged, validated)
// ------------------------------------------------------------------
#define GBM 128
#define GBN 128
#define GBK 16
__global__ __launch_bounds__(256) void gemm_bias(
    const float* __restrict__ A, const float* __restrict__ B,
    const float* __restrict__ bias, float* __restrict__ C,
    int M, int N, int K, const int* __restrict__ gather)
{
    __shared__ float As[GBK][GBM];
    __shared__ float Bs[GBK][GBN];

    const int tid = threadIdx.x;
    const int bm0 = blockIdx.y * GBM, bn0 = blockIdx.x * GBN;
    const int tx = tid & 15, ty = tid >> 4;

    float acc[8][8];
#pragma unroll
    for (int i = 0; i < 8; i++)
#pragma unroll
        for (int j = 0; j < 8; j++) acc[i][j] = 0.0f;

    int arow[8];
#pragma unroll
    for (int i = 0; i < 8; i++) {
        int m = (tid + i * 256) >> 4;
        int r = bm0 + m;
        arow[i] = gather ? gather[r] : r;
    }

    for (int k0 = 0; k0 < K; k0 += GBK) {
#pragma unroll
        for (int i = 0; i < 8; i++) {
            int lin = tid + i * 256;
            int m = lin >> 4, kk = lin & 15;
            As[kk][m] = A[(size_t)arow[i] * K + k0 + kk];
        }
#pragma unroll
        for (int i = 0; i < 8; i++) {
            int lin = tid + i * 256;
            int kk = lin >> 7, n = lin & 127;
            Bs[kk][n] = B[(size_t)(k0 + kk) * N + bn0 + n];
        }
        __syncthreads();
#pragma unroll
        for (int kk = 0; kk < GBK; kk++) {
            float a[8], bb[8];
#pragma unroll
            for (int i = 0; i < 8; i++) a[i]  = As[kk][ty * 8 + i];
#pragma unroll
            for (int j = 0; j < 8; j++) bb[j] = Bs[kk][tx * 8 + j];
#pragma unroll
            for (int i = 0; i < 8; i++)
#pragma unroll
                for (int j = 0; j < 8; j++) acc[i][j] = fmaf(a[i], bb[j], acc[i][j]);
        }
        __syncthreads();
    }

#pragma unroll
    for (int i = 0; i < 8; i++) {
        int row = bm0 + ty * 8 + i;
#pragma unroll
        for (int j = 0; j < 8; j++) {
            int col = bn0 + tx * 8 + j;
            C[(size_t)row * N + col] = acc[i][j] + bias[col];
        }
    }
}

// ------------------------------------------------------------------
// Persistent scan. 128 CTAs x 640 threads. CTA bx owns columns j0..j0+3.
//
// Pipelined schedule exploiting two independences:
//  (a) c_w(t) for words with start < t-1 is computed in step t-1's slack
//      ("early", overlapped with combine) and published by the step-end
//      barrier. Only start==t-1 words ("late") need a mid-step barrier,
//      and only on steps where such a masked word exists (g_nb1, ~22%).
//  (b) alpha = sig(xWa + c_w@Ua) is independent of the main gates, so
//      alpha dots (warps 4..19) overlap the main-gate dot (warps 0..3).
//
// Per step t (after prior step's gbar):
//   warps 0..3 : main-gate triple-dot (reads out[t-1]) -> s_iog
//   warps 4..19: late c_w if (mask[t,w] && start==t-1) -> g_cw[t&1]
//   if g_nb1[t]: gbar                     (publish late c_w)
//   warps 4..19: alpha dot over g_cw[t&1] (__ldcg: L1 staleness hazard)
//   __syncthreads
//   warp 0     : 16-lane combine -> out[t]
//   warps 4..19: EARLY c_w for t+1 if (mask && start<t) -> g_cw[(t+1)&1]
//   gbar                                   (publish out[t] + early c_w)
//
// g_cw/s_cwown double-buffered by parity: early writes target (t+1)&1
// while step-t readers use t&1. Mask/any/nb1 preprocessing runs in CTA0's
// prologue behind one initial barrier.
// ------------------------------------------------------------------
__global__ __launch_bounds__(NTH, 1) void scan_kernel(
    float* __restrict__ out,
    const int* __restrict__ wstarts,
    const unsigned char* __restrict__ mraw,
    const float* __restrict__ h0,
    const float* __restrict__ c0,
    const float* __restrict__ U,
    const float* __restrict__ Uw,
    const float* __restrict__ Ua)
{
    __shared__ float sUa[4 * 512];      // Ua columns j0..j0+3
    __shared__ float s_iog[12];         // sig(i),sig(o),tanh(g) per dj
    __shared__ float s_alpha[16];       // alpha[w*4+dj]
    __shared__ float s_cwown[2][16];    // c_w[w, j0+dj], double-buffered
    __shared__ int   s_det[2];          // mask dtype detection (CTA0)

    const int tid  = threadIdx.x;
    const int wg   = tid >> 5;
    const int lane = tid & 31;
    const int j0   = blockIdx.x * 4;

    // ---- CTA0 prologue: canonicalize word_mask (dtype unknown: int32 /
    //      float32 / uint8 hypotheses), compute g_any + g_nb1 ----
    if (blockIdx.x == 0) {
        if (tid == 0) { s_det[0] = 0; s_det[1] = 0; }
        __syncthreads();
        const unsigned int* w = (const unsigned int*)mraw;
        int li = 0, lf = 0;
        for (int i = tid; i < TT; i += NTH) {
            unsigned int v = w[i];
            if (v != 0u && v != 1u)          li = 1;
            if (v != 0u && v != 0x3f800000u) lf = 1;
        }
        if (li) atomicOr(&s_det[0], 1);
        if (lf) atomicOr(&s_det[1], 1);
        __syncthreads();
        int mode = (!s_det[0]) ? 1 : ((!s_det[1]) ? 2 : 0);
        for (int i = tid; i < TT * WNW; i += NTH) {
            unsigned char m;
            if (mode == 1)      m = (((const int*)  mraw)[i] != 0);
            else if (mode == 2) m = (((const float*)mraw)[i] != 0.0f);
            else                m = (mraw[i] != 0);
            g_mask[i] = m;
        }
        __syncthreads();
        for (int t = tid; t < TT; t += NTH) {
            int a = 0, nb = 0;
#pragma unroll
            for (int w4 = 0; w4 < WNW; w4++) {
                int m = g_mask[t * WNW + w4];
                a |= m;
                nb |= (m && (wstarts[t * WNW + w4] == t - 1));
            }
            g_any[t] = a;
            g_nb1[t] = nb;
        }
    }

    // ---- all CTAs: preload Ua slice (overlaps CTA0 prologue) ----
    for (int idx = tid; idx < 4 * 512; idx += NTH) {
        int dj = idx >> 9, k = idx & 511;
        sUa[idx] = Ua[(size_t)k * HH + j0 + dj];
    }

    // ---- per-warp gate weights to registers (lane l: k = l + 32m) ----
    const bool isU = (wg < 4);
    const int  dj  = isU ? wg : ((wg - 4) & 3);
    const int  wrd = isU ? 0  : ((wg - 4) >> 2);
    const int  jp  = j0 + dj;
    float wr0[16], wr1[16], wr2[16];
    {
        const float* M = isU ? U : Uw;
#pragma unroll
        for (int m = 0; m < 16; m++) {
            int k = lane + (m << 5);
            wr0[m] = M[(size_t)k * H3 + jp];
            wr1[m] = M[(size_t)k * H3 + 512 + jp];
            wr2[m] = M[(size_t)k * H3 + 1024 + jp];
        }
    }
    float cprev = (tid < 4) ? c0[j0 + tid] : 0.0f;

    unsigned int nbar = 1u;
    gbar_full(NB);                      // publish mask/any/nb1

    // ---- prime prefetch state for t=0 ----
    float pa0 = 0.f, pa1 = 0.f, pa2 = 0.f;   // main addends (lane 0)
    float an0 = 0.f, an1 = 0.f, an2 = 0.f;   // word addends (lane 0)
    float pxwa = 0.f;                        // alpha addend (word warps, lane 0)
    int   pws = 0;                           // word start (word warps, all lanes)
    int   pmw = 0;                           // word mask byte (word warps)
    unsigned int pmaskw = 0u;                // mask word (warp 0)
    int   panyt = g_any[0];
    int   pnb   = g_nb1[0];

    if (isU) {
        if (lane == 0) {
            pa0 = __ldg(&g_xW[jp]);
            pa1 = __ldg(&g_xW[512 + jp]);
            pa2 = __ldg(&g_xW[1024 + jp]);
        }
    } else {
        if (lane == 0) {
            const float* src = g_gwX + (size_t)wrd * H3;
            an0 = __ldg(src + jp);
            an1 = __ldg(src + 512 + jp);
            an2 = __ldg(src + 1024 + jp);
            pxwa = __ldg(&g_xWa[jp]);
        }
        pws = __ldg(&wstarts[wrd]);
        pmw = g_mask[wrd];
    }
    if (wg == 0) pmaskw = *(const unsigned int*)&g_mask[0];
    __syncthreads();

    for (int t = 0; t < TT; t++) {
        const int tn = (t + 1 < TT) ? t + 1 : t;
        const int cur_any = panyt;
        const int cur_nb  = pnb;
        panyt = g_any[tn];
        pnb   = g_nb1[tn];
        float addb = pxwa;                    // alpha addend for step t

        if (isU) {
            // ---- main-gate triple-dot ----
            const float* vec = (t == 0) ? h0 : (out + (size_t)(t - 1) * 1024);
            float add0 = pa0, add1 = pa1, add2 = pa2;
            if (lane == 0) {
                const float* src = g_xW + (size_t)tn * H3;
                pa0 = __ldg(src + jp);
                pa1 = __ldg(src + 512 + jp);
                pa2 = __ldg(src + 1024 + jp);
            }
            float a0 = 0.f, a1 = 0.f, a2 = 0.f;
#pragma unroll
            for (int m = 0; m < 16; m++) {
                float hv = vec[lane + (m << 5)];
                a0 = fmaf(hv, wr0[m], a0);
                a1 = fmaf(hv, wr1[m], a1);
                a2 = fmaf(hv, wr2[m], a2);
            }
            a0 = wsum(a0); a1 = wsum(a1); a2 = wsum(a2);
            if (lane == 0) {
                s_iog[dj * 3 + 0] = fsig(add0 + a0);
                s_iog[dj * 3 + 1] = fsig(add1 + a1);
                s_iog[dj * 3 + 2] = ftanh(add2 + a2);
            }
        } else {
            // ---- rotate word-warp state; handle LATE word (start==t-1) ----
            float al0 = an0, al1 = an1, al2 = an2;
            int   as = pws, am = pmw;
            if (lane == 0) {
                const float* src = g_gwX + (size_t)(tn * WNW + wrd) * H3;
                an0 = __ldg(src + jp);
                an1 = __ldg(src + 512 + jp);
                an2 = __ldg(src + 1024 + jp);
                pxwa = __ldg(&g_xWa[(size_t)tn * HH + jp]);
            }
            pws = __ldg(&wstarts[tn * WNW + wrd]);
            pmw = g_mask[tn * WNW + wrd];

            if (am && as == t - 1) {          // late word-cell for step t
                const float* vec = out + (size_t)as * 1024;
                float csv = (lane == 0) ? out[(size_t)as * 1024 + 512 + jp] : 0.f;
                float a0 = 0.f, a1 = 0.f, a2 = 0.f;
#pragma unroll
                for (int m = 0; m < 16; m++) {
                    float hv = vec[lane + (m << 5)];
                    a0 = fmaf(hv, wr0[m], a0);
                    a1 = fmaf(hv, wr1[m], a1);
                    a2 = fmaf(hv, wr2[m], a2);
                }
                a0 = wsum(a0); a1 = wsum(a1); a2 = wsum(a2);
                if (lane == 0) {
                    float cwv = fsig(al0 + a0) * csv
                              + fsig(al1 + a1) * ftanh(al2 + a2);
                    g_cw[t & 1][wrd * 512 + jp] = cwv;
                    s_cwown[t & 1][wrd * 4 + dj] = cwv;
                }
            }
        }

        if (cur_nb) gbar_full(++nbar * NB);   // publish late c_w (~22% steps)

        // ---- alpha dots (word warps), overlapped with main dot above ----
        if (cur_any && !isU) {
            const float* cv = g_cw[t & 1] + wrd * 512;
            const float* ua = sUa + dj * 512;
            float a = 0.f;
#pragma unroll
            for (int m = 0; m < 16; m++) {
                int k = lane + (m << 5);
                a = fmaf(__ldcg(cv + k), ua[k], a);   // ldcg: L1 would be stale
            }
            a = wsum(a);
            if (lane == 0) s_alpha[wrd * 4 + dj] = fsig(addb + a);
        }
        __syncthreads();

        // ---- combine (warp 0) || EARLY word-cells for t+1 (warps 4..19) ----
        if (wg == 0) {
            unsigned int cm = pmaskw;
            pmaskw = *(const unsigned int*)&g_mask[tn * WNW];
            const int w  = (lane >> 2) & 3;
            const int dc = lane & 3;
            float ew = 0.f, nm = 0.f;
            if (cur_any && ((cm >> (8 * w)) & 0xffu)) {
                ew = __expf(s_alpha[w * 4 + dc]);
                nm = ew * s_cwown[t & 1][w * 4 + dc];
            }
            ew += __shfl_xor_sync(0xffffffffu, ew, 4);
            nm += __shfl_xor_sync(0xffffffffu, nm, 4);
            ew += __shfl_xor_sync(0xffffffffu, ew, 8);
            nm += __shfl_xor_sync(0xffffffffu, nm, 8);
            if (lane < 4) {
                float ig = s_iog[lane * 3 + 0];
                float og = s_iog[lane * 3 + 1];
                float gg = s_iog[lane * 3 + 2];
                float c1;
                if (cur_any) {
                    float e0 = __expf(ig);
                    c1 = __fdividef(fmaf(e0, gg, nm), e0 + ew);
                } else {
                    c1 = (1.0f - ig) * cprev + ig * gg;
                }
                float h1 = og * ftanh(c1);
                out[(size_t)t * 1024 + j0 + lane]       = h1;
                out[(size_t)t * 1024 + 512 + j0 + lane] = c1;
                cprev = c1;
            }
        } else if (!isU) {
            // early word-cell for step t+1: start < t -> row already published
            if (pmw && pws < t) {
                const float* vec = out + (size_t)pws * 1024;
                float csv = (lane == 0) ? out[(size_t)pws * 1024 + 512 + jp] : 0.f;
                float a0 = 0.f, a1 = 0.f, a2 = 0.f;
#pragma unroll
                for (int m = 0; m < 16; m++) {
                    float hv = vec[lane + (m << 5)];
                    a0 = fmaf(hv, wr0[m], a0);
                    a1 = fmaf(hv, wr1[m], a1);
                    a2 = fmaf(hv, wr2[m], a2);
                }
                a0 = wsum(a0); a1 = wsum(a1); a2 = wsum(a2);
                if (lane == 0) {
                    float cwv = fsig(an0 + a0) * csv
                              + fsig(an1 + a1) * ftanh(an2 + a2);
                    g_cw[(t + 1) & 1][wrd * 512 + jp] = cwv;
                    s_cwown[(t + 1) & 1][wrd * 4 + dj] = cwv;
                }
            }
        }
        if (t < TT - 1) gbar_full(++nbar * NB);   // publish out[t] + early c_w
    }
}

// ------------------------------------------------------------------
// Launch. Input order (metadata): x, word_ids, word_starts, word_mask,
// h0, c0, emb, W, U, b, Wa, Ua, ba, Ww, Uw, bw.  Output: [T, 2H] f32.
// Order: 3 gemms, scan (launch #4 -> ncu -s 5 lands on it), reset.
// ------------------------------------------------------------------
extern "C" void kernel_launch(void* const* d_in, const int* in_sizes, int n_in,
                              void* d_out, int out_size)
{
    const float*         x        = (const float*)d_in[0];
    const int*           word_ids = (const int*)  d_in[1];
    const int*           wstarts  = (const int*)  d_in[2];
    const unsigned char* mraw     = (const unsigned char*)d_in[3];
    const float*         h0       = (const float*)d_in[4];
    const float*         c0       = (const float*)d_in[5];
    const float*         emb      = (const float*)d_in[6];
    const float*         W        = (const float*)d_in[7];
    const float*         U        = (const float*)d_in[8];
    const float*         b        = (const float*)d_in[9];
    const float*         Wa       = (const float*)d_in[10];
    const float*         Ua       = (const float*)d_in[11];
    const float*         ba       = (const float*)d_in[12];
    const float*         Ww       = (const float*)d_in[13];
    const float*         Uw       = (const float*)d_in[14];
    const float*         bw       = (const float*)d_in[15];
    float*               out      = (float*)d_out;

    (void)in_sizes; (void)n_in; (void)out_size;

    void *pxW = nullptr, *pxWa = nullptr, *pgwX = nullptr;
    cudaGetSymbolAddress(&pxW,  g_xW);
    cudaGetSymbolAddress(&pxWa, g_xWa);
    cudaGetSymbolAddress(&pgwX, g_gwX);

    // xW  = x @ W  + b    : [4096,128]@[128,1536]
    gemm_bias<<<dim3(H3 / GBN, TT / GBM), 256>>>(
        x, W, b, (float*)pxW, TT, H3, DD, nullptr);
    // xWa = x @ Wa + ba   : [4096,128]@[128,512]
    gemm_bias<<<dim3(HH / GBN, TT / GBM), 256>>>(
        x, Wa, ba, (float*)pxWa, TT, HH, DD, nullptr);
    // gwX = emb[word_ids] @ Ww + bw : [16384,256]@[256,1536]
    gemm_bias<<<dim3(H3 / GBN, (TT * WNW) / GBM), 256>>>(
        emb, Ww, bw, (float*)pgwX, TT * WNW, H3, EE, word_ids);

    scan_kernel<<<NB, NTH>>>(out, wstarts, mraw, h0, c0, U, Uw, Ua);

    reset_kernel<<<1, 32>>>();   // clean barrier counter for next replay
}